// round 2
// baseline (speedup 1.0000x reference)
#include <cuda_runtime.h>

// RoIMaskAlign: features (B=2, C=256, H=200, W=272) fp32, rois (K=256, 5) fp32
// out (K, C, 14, 14) fp32
// PH=PW=14, SPATIAL_SCALE=0.25, SR=2, SPATIAL_SHIFT=0, HALF_PART=0, ROI_SCALE=1.2

#define PH 14
#define PW 14

static constexpr int   Cc = 256;
static constexpr int   Hc = 200;
static constexpr int   Wc = 272;
static constexpr float SCALE     = 0.25f;
static constexpr float ROI_SCALE = 1.2f;

// Select f[e] for e in 0..3, predicates precomputed.
__device__ __forceinline__ float sel4(const float4& f, bool b0, bool b1) {
    // b0 = (e & 1), b1 = (e & 2)
    float lo = b0 ? f.y : f.x;
    float hi = b0 ? f.w : f.z;
    return b1 ? hi : lo;
}

// Select element e+1 from window: candidates f.y (e=0), f.z (e=1), f.w (e=2), s (e=3)
__device__ __forceinline__ float sel_next(const float4& f, float s,
                                          bool pe1, bool pe2, bool pe3) {
    float t = pe1 ? f.z : f.y;
    t = pe2 ? f.w : t;
    return pe3 ? s : t;
}

__global__ __launch_bounds__(196)
void roi_mask_align_kernel(const float* __restrict__ feat,
                           const float* __restrict__ rois,
                           float* __restrict__ out)
{
    // block -> (n, c) plane; thread -> (ph, pw)
    int nc = blockIdx.x;          // 0 .. K*C-1
    int c  = nc & (Cc - 1);
    int n  = nc >> 8;             // Cc == 256
    int t  = threadIdx.x;         // 0 .. 195
    int pw = t % PW;
    int ph = t / PW;

    // ROI params (warp-uniform: whole block is one ROI)
    const float* r = rois + n * 5;
    int   b  = (int)r[0];
    float x1 = r[1], y1 = r[2], x2 = r[3], y2 = r[4];

    float cx = (x1 + x2) * 0.5f;
    float cy = (y1 + y2) * 0.5f;
    float w  = (x2 - x1) * ROI_SCALE;
    float h  = (y2 - y1) * ROI_SCALE;
    float x1s = (cx - 0.5f * w) * SCALE;
    float x2s = (cx + 0.5f * w) * SCALE;
    float y1s = (cy - 0.5f * h) * SCALE;
    float y2s = (cy + 0.5f * h) * SCALE;

    float roi_w = fmaxf(x2s - x1s, 1.0f);
    float roi_h = fmaxf(y2s - y1s, 1.0f);
    float bin_w = roi_w * (1.0f / PW);
    float bin_h = roi_h * (1.0f / PH);

    const float* fb = feat + ((size_t)(b * Cc + c)) * (Hc * Wc);

    // ---- per-sample x data (shared by both sy rows) ----
    int   a[2];            // aligned float4 base (element index), always in-row
    int   x1i[2];          // clamped x0+1 for the e==3 scalar fallback
    float lx[2], hx[2];
    bool  vx[2];
    bool  pb0[2], pb1[2];            // e&1, e&2
    bool  pe1[2], pe2[2], pe3[2];    // e==1, e>=2, e==3

    #pragma unroll
    for (int sx = 0; sx < 2; sx++) {
        float x = x1s + ((float)pw + ((float)sx + 0.5f) * 0.5f) * bin_w;
        vx[sx] = (x > -1.0f) && (x < (float)Wc);
        float xc = fminf(fmaxf(x, 0.0f), (float)(Wc - 1));
        int x0 = (int)floorf(xc);
        int e  = x0 & 3;
        a[sx]   = x0 - e;                 // 16B-aligned, a+3 <= Wc-1 always
        x1i[sx] = min(x0 + 1, Wc - 1);
        lx[sx] = xc - (float)x0;
        hx[sx] = 1.0f - lx[sx];
        pb0[sx] = (e & 1) != 0;
        pb1[sx] = (e & 2) != 0;
        pe1[sx] = (e == 1);
        pe2[sx] = (e >= 2);
        pe3[sx] = (e == 3);
    }

    float sum = 0.0f;
    #pragma unroll
    for (int sy = 0; sy < 2; sy++) {
        float y = y1s + ((float)ph + ((float)sy + 0.5f) * 0.5f) * bin_h;
        bool vy = (y > -1.0f) && (y < (float)Hc);
        float yc = fminf(fmaxf(y, 0.0f), (float)(Hc - 1));
        int y0 = (int)floorf(yc);
        int y1b = min(y0 + 1, Hc - 1);
        float ly = yc - (float)y0;
        float hy = 1.0f - ly;

        const float* row0 = fb + (size_t)y0  * Wc;
        const float* row1 = fb + (size_t)y1b * Wc;

        // 4 vector loads (2 rows x 2 samples), issued together for MLP
        float4 w00 = __ldg((const float4*)(row0 + a[0]));
        float4 w01 = __ldg((const float4*)(row0 + a[1]));
        float4 w10 = __ldg((const float4*)(row1 + a[0]));
        float4 w11 = __ldg((const float4*)(row1 + a[1]));

        // predicated scalar fixups (needed only when e==3, ~25% of lanes)
        float s00 = 0.f, s01 = 0.f, s10 = 0.f, s11 = 0.f;
        if (pe3[0]) { s00 = __ldg(row0 + x1i[0]); s10 = __ldg(row1 + x1i[0]); }
        if (pe3[1]) { s01 = __ldg(row0 + x1i[1]); s11 = __ldg(row1 + x1i[1]); }

        // sample sx=0
        {
            float v00 = sel4(w00, pb0[0], pb1[0]);
            float v01 = sel_next(w00, s00, pe1[0], pe2[0], pe3[0]);
            float v10 = sel4(w10, pb0[0], pb1[0]);
            float v11 = sel_next(w10, s10, pe1[0], pe2[0], pe3[0]);
            float top = hx[0] * v00 + lx[0] * v01;
            float bot = hx[0] * v10 + lx[0] * v11;
            float val = hy * top + ly * bot;
            sum += (vy && vx[0]) ? val : 0.0f;
        }
        // sample sx=1
        {
            float v00 = sel4(w01, pb0[1], pb1[1]);
            float v01 = sel_next(w01, s01, pe1[1], pe2[1], pe3[1]);
            float v10 = sel4(w11, pb0[1], pb1[1]);
            float v11 = sel_next(w11, s11, pe1[1], pe2[1], pe3[1]);
            float top = hx[1] * v00 + lx[1] * v01;
            float bot = hx[1] * v10 + lx[1] * v11;
            float val = hy * top + ly * bot;
            sum += (vy && vx[1]) ? val : 0.0f;
        }
    }

    out[(size_t)nc * (PH * PW) + t] = sum * 0.25f;
}

extern "C" void kernel_launch(void* const* d_in, const int* in_sizes, int n_in,
                              void* d_out, int out_size)
{
    const float* feat = (const float*)d_in[0];
    const float* rois = (const float*)d_in[1];
    float* out = (float*)d_out;

    int blocks = out_size / (PH * PW);   // K * C
    roi_mask_align_kernel<<<blocks, PH * PW>>>(feat, rois, out);
}